// round 2
// baseline (speedup 1.0000x reference)
#include <cuda_runtime.h>
#include <math.h>

// Problem constants
#define BATCH 2
#define TSEQ  1024
#define HDIM  1024
#define NTOK  (BATCH*TSEQ)     // 2048
#define NHEAD 16
#define NKVH  4
#define HEADD 64
#define NEXP  64
#define TOPK  8
#define IDIM  512

// ---------------- scratch (device globals; no allocations allowed) ----------
__device__ float g_h[NTOK*HDIM];            // rmsnorm1 out
__device__ float g_q[NTOK*NHEAD*HEADD];
__device__ float g_k[NTOK*NKVH*HEADD];
__device__ float g_v[NTOK*NKVH*HEADD];
__device__ float g_ao[NTOK*HDIM];           // attention out (pre-Wo)
__device__ float g_f[NTOK*HDIM];            // rmsnorm2 out
__device__ int   g_cnt[NEXP];
__device__ int   g_elist[NEXP*NTOK];
__device__ float g_escore[NEXP*NTOK];
__device__ float g_gbuf[NEXP*NTOK*IDIM];    // 256MB: per-expert-slot intermediate g

// ---------------- rmsnorm ---------------------------------------------------
__global__ void rmsnorm_kernel(const float* __restrict__ x,
                               const float* __restrict__ w,
                               float* __restrict__ o) {
    int row = blockIdx.x;
    const float* xr = x + (size_t)row * HDIM;
    __shared__ float red[256];
    float s = 0.f;
    for (int i = threadIdx.x; i < HDIM; i += 256) { float v = xr[i]; s += v * v; }
    red[threadIdx.x] = s;
    __syncthreads();
    for (int st = 128; st > 0; st >>= 1) {
        if (threadIdx.x < st) red[threadIdx.x] += red[threadIdx.x + st];
        __syncthreads();
    }
    float inv = rsqrtf(red[0] / (float)HDIM + 1e-6f);
    for (int i = threadIdx.x; i < HDIM; i += 256)
        o[(size_t)row * HDIM + i] = xr[i] * inv * w[i];
}

// ---------------- generic fp32 tiled GEMM: C = A@B (+R) ---------------------
// BM=BN=64, BK=16, 256 threads, 4x4 per thread. M,N,K multiples of tile dims.
__global__ void gemm_kernel(const float* __restrict__ A, const float* __restrict__ B,
                            const float* __restrict__ R, float* __restrict__ C,
                            int M, int N, int K) {
    __shared__ float As[16][64];
    __shared__ float Bs[16][64];
    int bx = blockIdx.x * 64, by = blockIdx.y * 64;
    int t = threadIdx.x;
    int tx = t & 15, ty = t >> 4;
    float acc[4][4] = {};
    for (int k0 = 0; k0 < K; k0 += 16) {
        #pragma unroll
        for (int i = 0; i < 4; i++) {
            int idx = t + i * 256;
            int r = idx >> 4, c = idx & 15;
            As[c][r] = A[(size_t)(by + r) * K + k0 + c];
            int r2 = idx >> 6, c2 = idx & 63;
            Bs[r2][c2] = B[(size_t)(k0 + r2) * N + bx + c2];
        }
        __syncthreads();
        #pragma unroll
        for (int k = 0; k < 16; k++) {
            float a[4], b[4];
            #pragma unroll
            for (int i = 0; i < 4; i++) a[i] = As[k][ty * 4 + i];
            #pragma unroll
            for (int j = 0; j < 4; j++) b[j] = Bs[k][tx * 4 + j];
            #pragma unroll
            for (int i = 0; i < 4; i++)
                #pragma unroll
                for (int j = 0; j < 4; j++) acc[i][j] += a[i] * b[j];
        }
        __syncthreads();
    }
    #pragma unroll
    for (int i = 0; i < 4; i++)
        #pragma unroll
        for (int j = 0; j < 4; j++) {
            int r = by + ty * 4 + i, c = bx + tx * 4 + j;
            float v = acc[i][j];
            if (R) v += R[(size_t)r * N + c];
            C[(size_t)r * N + c] = v;
        }
}

// ---------------- RoPE (in place) -------------------------------------------
__global__ void rope_kernel(float* __restrict__ q, const float* __restrict__ cs,
                            const float* __restrict__ sn, int nheads) {
    int idx = blockIdx.x * blockDim.x + threadIdx.x;
    int total = NTOK * nheads * 32;
    if (idx >= total) return;
    int d  = idx & 31;
    int hh = (idx >> 5) % nheads;
    int n  = idx / (32 * nheads);
    int tp = n % TSEQ;
    float c0 = cs[tp * HEADD + d],      s0 = sn[tp * HEADD + d];
    float c1 = cs[tp * HEADD + d + 32], s1 = sn[tp * HEADD + d + 32];
    float* base = q + ((size_t)n * nheads + hh) * HEADD;
    float v0 = base[d], v1 = base[d + 32];
    base[d]      = v0 * c0 - v1 * s0;
    base[d + 32] = v1 * c1 + v0 * s1;
}

// ---------------- causal flash attention (one 64-thread block per q row) ----
__global__ void attn_kernel(const float* __restrict__ Q, const float* __restrict__ Kk,
                            const float* __restrict__ V, float* __restrict__ O) {
    int qrow = blockIdx.x, h = blockIdx.y, b = blockIdx.z;
    int kvh = h / (NHEAD / NKVH);
    int t = threadIdx.x;  // 0..63: key index in score phase, dim index in acc phase
    __shared__ float Ks[64][65];
    __shared__ float Vs[64][65];
    __shared__ float qs[64];
    __shared__ float ps[64];
    int n = b * TSEQ + qrow;
    qs[t] = Q[((size_t)n * NHEAD + h) * HEADD + t];
    float m = -1e30f, l = 0.f, acc = 0.f;
    for (int t0 = 0; t0 <= qrow; t0 += 64) {
        int nk = min(64, qrow - t0 + 1);
        __syncthreads();  // previous tile fully consumed (and qs visible on iter 0)
        for (int i = 0; i < 64; i++) {
            int key = t0 + i; if (key > qrow) key = qrow;   // clamped, masked below
            int kn = b * TSEQ + key;
            Ks[i][t] = Kk[((size_t)kn * NKVH + kvh) * HEADD + t];
            Vs[i][t] = V [((size_t)kn * NKVH + kvh) * HEADD + t];
        }
        __syncthreads();
        float s;
        if (t < nk) {
            s = 0.f;
            #pragma unroll
            for (int dd = 0; dd < 64; dd++) s += qs[dd] * Ks[t][dd];
            s *= 0.125f;  // 1/sqrt(64)
        } else s = -1e30f;
        ps[t] = s;
        __syncthreads();
        float tmax = -1e30f;
        for (int j = 0; j < 64; j++) tmax = fmaxf(tmax, ps[j]);
        float newm = fmaxf(m, tmax);
        float pe = (t < nk) ? expf(s - newm) : 0.f;
        __syncthreads();
        ps[t] = pe;
        __syncthreads();
        float corr = expf(m - newm);
        float psum = 0.f, av = 0.f;
        for (int j = 0; j < nk; j++) { float p = ps[j]; psum += p; av += p * Vs[j][t]; }
        l   = l   * corr + psum;
        acc = acc * corr + av;
        m = newm;
    }
    O[(size_t)n * HDIM + h * HEADD + t] = acc / l;
}

// ---------------- router: per-token top-8 + expert list build ---------------
__global__ void zero_cnt_kernel(int* __restrict__ cnt) {
    if (threadIdx.x < NEXP) cnt[threadIdx.x] = 0;
}

__global__ void router_topk_kernel(const float* __restrict__ logits,
                                   int* __restrict__ cnt, int* __restrict__ elist,
                                   float* __restrict__ escore) {
    int n = blockIdx.x * blockDim.x + threadIdx.x;
    if (n >= NTOK) return;
    float lg[NEXP];
    for (int e = 0; e < NEXP; e++) lg[e] = logits[(size_t)n * NEXP + e];
    int sel[TOPK]; float sv[TOPK];
    for (int k = 0; k < TOPK; k++) {
        float best = -1e30f; int bi = 0;
        for (int e = 0; e < NEXP; e++)
            if (lg[e] > best) { best = lg[e]; bi = e; }
        sel[k] = bi; sv[k] = best; lg[bi] = -1e30f;
    }
    // normalized softmax weights restricted to the selected set
    float mx = sv[0];
    float ssum = 0.f;
    for (int k = 0; k < TOPK; k++) { sv[k] = expf(sv[k] - mx); ssum += sv[k]; }
    for (int k = 0; k < TOPK; k++) {
        int e = sel[k];
        int pos = atomicAdd(&cnt[e], 1);
        elist[e * NTOK + pos]  = n;
        escore[e * NTOK + pos] = sv[k] / ssum;
    }
}

// ---------------- MoE gate/up: gathered GEMM + fused SiLU -------------------
__global__ void moe_gateup_kernel(const float* __restrict__ F, const float* __restrict__ Wg,
                                  const float* __restrict__ Wu,
                                  const int* __restrict__ cnt, const int* __restrict__ elist,
                                  float* __restrict__ G) {
    int e = blockIdx.z;
    int c = cnt[e];
    int t0 = blockIdx.y * 64;
    if (t0 >= c) return;
    int ic0 = blockIdx.x * 64;
    const float* Bg = Wg + (size_t)e * HDIM * IDIM;
    const float* Bu = Wu + (size_t)e * HDIM * IDIM;
    __shared__ float As[16][64];
    __shared__ float Gs[16][64];
    __shared__ float Us[16][64];
    __shared__ int rows[64];
    int t = threadIdx.x;
    if (t < 64) {
        int tr = t0 + t;
        rows[t] = elist[e * NTOK + ((tr < c) ? tr : t0)];
    }
    __syncthreads();
    int tx = t & 15, ty = t >> 4;
    float ag[4][4] = {}, au[4][4] = {};
    for (int k0 = 0; k0 < HDIM; k0 += 16) {
        #pragma unroll
        for (int i = 0; i < 4; i++) {
            int idx = t + i * 256;
            int r = idx >> 4, cc = idx & 15;
            As[cc][r] = F[(size_t)rows[r] * HDIM + k0 + cc];
            int r2 = idx >> 6, c2 = idx & 63;
            Gs[r2][c2] = Bg[(size_t)(k0 + r2) * IDIM + ic0 + c2];
            Us[r2][c2] = Bu[(size_t)(k0 + r2) * IDIM + ic0 + c2];
        }
        __syncthreads();
        #pragma unroll
        for (int k = 0; k < 16; k++) {
            float a[4], bg[4], bu[4];
            #pragma unroll
            for (int i = 0; i < 4; i++) a[i] = As[k][ty * 4 + i];
            #pragma unroll
            for (int j = 0; j < 4; j++) { bg[j] = Gs[k][tx * 4 + j]; bu[j] = Us[k][tx * 4 + j]; }
            #pragma unroll
            for (int i = 0; i < 4; i++)
                #pragma unroll
                for (int j = 0; j < 4; j++) {
                    ag[i][j] += a[i] * bg[j];
                    au[i][j] += a[i] * bu[j];
                }
        }
        __syncthreads();
    }
    #pragma unroll
    for (int i = 0; i < 4; i++) {
        int tr = t0 + ty * 4 + i;
        if (tr >= c) continue;
        #pragma unroll
        for (int j = 0; j < 4; j++) {
            float g = ag[i][j];
            float val = g / (1.f + expf(-g)) * au[i][j];  // silu(g) * up
            G[((size_t)e * NTOK + tr) * IDIM + ic0 + tx * 4 + j] = val;
        }
    }
}

// ---------------- MoE down: per-expert GEMM + score-scaled scatter ----------
__global__ void moe_down_kernel(const float* __restrict__ G, const float* __restrict__ Wd,
                                const int* __restrict__ cnt, const int* __restrict__ elist,
                                const float* __restrict__ escore, float* __restrict__ out) {
    int e = blockIdx.z;
    int c = cnt[e];
    int t0 = blockIdx.y * 64;
    if (t0 >= c) return;
    int hc0 = blockIdx.x * 64;
    const float* Am = G  + (size_t)e * NTOK * IDIM;
    const float* Bm = Wd + (size_t)e * IDIM * HDIM;
    __shared__ float As[16][64];
    __shared__ float Bs[16][64];
    int t = threadIdx.x;
    int tx = t & 15, ty = t >> 4;
    float acc[4][4] = {};
    for (int k0 = 0; k0 < IDIM; k0 += 16) {
        #pragma unroll
        for (int i = 0; i < 4; i++) {
            int idx = t + i * 256;
            int r = idx >> 4, cc = idx & 15;
            As[cc][r] = Am[(size_t)(t0 + r) * IDIM + k0 + cc];  // rows>=c: stale finite, masked
            int r2 = idx >> 6, c2 = idx & 63;
            Bs[r2][c2] = Bm[(size_t)(k0 + r2) * HDIM + hc0 + c2];
        }
        __syncthreads();
        #pragma unroll
        for (int k = 0; k < 16; k++) {
            float a[4], b[4];
            #pragma unroll
            for (int i = 0; i < 4; i++) a[i] = As[k][ty * 4 + i];
            #pragma unroll
            for (int j = 0; j < 4; j++) b[j] = Bs[k][tx * 4 + j];
            #pragma unroll
            for (int i = 0; i < 4; i++)
                #pragma unroll
                for (int j = 0; j < 4; j++) acc[i][j] += a[i] * b[j];
        }
        __syncthreads();
    }
    #pragma unroll
    for (int i = 0; i < 4; i++) {
        int tr = t0 + ty * 4 + i;
        if (tr >= c) continue;
        int n   = elist[e * NTOK + tr];
        float s = escore[e * NTOK + tr];
        #pragma unroll
        for (int j = 0; j < 4; j++)
            atomicAdd(&out[(size_t)n * HDIM + hc0 + tx * 4 + j], acc[i][j] * s);
    }
}

// ---------------- launch ----------------------------------------------------
extern "C" void kernel_launch(void* const* d_in, const int* in_sizes, int n_in,
                              void* d_out, int out_size) {
    const float* x    = (const float*)d_in[0];
    const float* cosb = (const float*)d_in[1];
    const float* sinb = (const float*)d_in[2];
    const float* ln1  = (const float*)d_in[3];
    const float* ln2  = (const float*)d_in[4];
    const float* Wq   = (const float*)d_in[5];
    const float* Wk   = (const float*)d_in[6];
    const float* Wv   = (const float*)d_in[7];
    const float* Wo   = (const float*)d_in[8];
    const float* Wr   = (const float*)d_in[9];
    const float* Wg   = (const float*)d_in[10];
    const float* Wu   = (const float*)d_in[11];
    const float* Wd   = (const float*)d_in[12];
    float* out = (float*)d_out;             // (B,T,H) region
    float* rl  = out + (size_t)NTOK * HDIM; // router_logits region

    float *h, *q, *k, *v, *ao, *f, *gb, *es;
    int *cnt, *el;
    cudaGetSymbolAddress((void**)&h,   g_h);
    cudaGetSymbolAddress((void**)&q,   g_q);
    cudaGetSymbolAddress((void**)&k,   g_k);
    cudaGetSymbolAddress((void**)&v,   g_v);
    cudaGetSymbolAddress((void**)&ao,  g_ao);
    cudaGetSymbolAddress((void**)&f,   g_f);
    cudaGetSymbolAddress((void**)&gb,  g_gbuf);
    cudaGetSymbolAddress((void**)&es,  g_escore);
    cudaGetSymbolAddress((void**)&cnt, g_cnt);
    cudaGetSymbolAddress((void**)&el,  g_elist);

    // 1. h = rmsnorm(x, ln1_w)
    rmsnorm_kernel<<<NTOK, 256>>>(x, ln1, h);
    // 2. QKV projections
    gemm_kernel<<<dim3(16, 32), 256>>>(h, Wq, nullptr, q, NTOK, 1024, 1024);
    gemm_kernel<<<dim3(4,  32), 256>>>(h, Wk, nullptr, k, NTOK,  256, 1024);
    gemm_kernel<<<dim3(4,  32), 256>>>(h, Wv, nullptr, v, NTOK,  256, 1024);
    // 3. RoPE on q and k
    rope_kernel<<<(NTOK * NHEAD * 32 + 255) / 256, 256>>>(q, cosb, sinb, NHEAD);
    rope_kernel<<<(NTOK * NKVH  * 32 + 255) / 256, 256>>>(k, cosb, sinb, NKVH);
    // 4. causal attention
    attn_kernel<<<dim3(TSEQ, NHEAD, BATCH), 64>>>(q, k, v, ao);
    // 5. x1 = x + ao@Wo  (written directly into d_out)
    gemm_kernel<<<dim3(16, 32), 256>>>(ao, Wo, x, out, NTOK, 1024, 1024);
    // 6. f = rmsnorm(x1, ln2_w)
    rmsnorm_kernel<<<NTOK, 256>>>(out, ln2, f);
    // 7. router logits (written directly into d_out tail)
    gemm_kernel<<<dim3(1, 32), 256>>>(f, Wr, nullptr, rl, NTOK, NEXP, 1024);
    // 8-9. top-k + expert lists
    zero_cnt_kernel<<<1, 64>>>(cnt);
    router_topk_kernel<<<NTOK / 256, 256>>>(rl, cnt, el, es);
    // 10. gate/up + silu (sparse, expert-grouped)
    moe_gateup_kernel<<<dim3(IDIM / 64, NTOK / 64, NEXP), 256>>>(f, Wg, Wu, cnt, el, gb);
    // 11. down + scaled scatter onto residual in d_out
    moe_down_kernel<<<dim3(HDIM / 64, NTOK / 64, NEXP), 256>>>(gb, Wd, cnt, el, es, out);
}

// round 4
// speedup vs baseline: 3.2543x; 3.2543x over previous
#include <cuda_runtime.h>
#include <stdint.h>
#include <math.h>

// Problem constants
#define BATCH 2
#define TSEQ  1024
#define HDIM  1024
#define NTOK  (BATCH*TSEQ)     // 2048
#define NHEAD 16
#define NKVH  4
#define HEADD 64
#define NEXP  64
#define TOPK  8
#define IDIM  512

// ---------------- scratch (device globals; no allocations allowed) ----------
__device__ __align__(256) float g_h[NTOK*HDIM];
__device__ __align__(256) float g_q[NTOK*NHEAD*HEADD];
__device__ __align__(256) float g_k[NTOK*NKVH*HEADD];
__device__ __align__(256) float g_v[NTOK*NKVH*HEADD];
__device__ __align__(256) float g_ao[NTOK*HDIM];
__device__ __align__(256) float g_f[NTOK*HDIM];
__device__ int   g_cnt[NEXP];
__device__ int   g_elist[NEXP*NTOK];
__device__ float g_escore[NEXP*NTOK];
__device__ __align__(256) float g_gbuf[(size_t)NEXP*NTOK*IDIM];

// ---------------- helpers ----------------------------------------------------
__device__ __forceinline__ float tf32r(float x) {
    uint32_t u;
    asm("cvt.rna.tf32.f32 %0, %1;" : "=r"(u) : "f"(x));
    return __uint_as_float(u);
}

__device__ __forceinline__ void mma8(float* c, const uint32_t* a, const uint32_t* b) {
    asm volatile(
        "mma.sync.aligned.m16n8k8.row.col.f32.tf32.tf32.f32 "
        "{%0,%1,%2,%3}, {%4,%5,%6,%7}, {%8,%9}, {%0,%1,%2,%3};"
        : "+f"(c[0]), "+f"(c[1]), "+f"(c[2]), "+f"(c[3])
        : "r"(a[0]), "r"(a[1]), "r"(a[2]), "r"(a[3]), "r"(b[0]), "r"(b[1]));
}

// ---------------- rmsnorm ---------------------------------------------------
__global__ void rmsnorm_kernel(const float* __restrict__ x,
                               const float* __restrict__ w,
                               float* __restrict__ o) {
    int row = blockIdx.x;
    const float* xr = x + (size_t)row * HDIM;
    __shared__ float red[256];
    float s = 0.f;
    for (int i = threadIdx.x; i < HDIM; i += 256) { float v = xr[i]; s += v * v; }
    red[threadIdx.x] = s;
    __syncthreads();
    for (int st = 128; st > 0; st >>= 1) {
        if (threadIdx.x < st) red[threadIdx.x] += red[threadIdx.x + st];
        __syncthreads();
    }
    float inv = rsqrtf(red[0] / (float)HDIM + 1e-6f);
    for (int i = threadIdx.x; i < HDIM; i += 256)
        o[(size_t)row * HDIM + i] = xr[i] * inv * w[i];
}

// ---------------- tf32 tensor-core GEMM ------------------------------------
// 128x128x16 tile, 256 threads (8 warps as 2x4, each warp 64x32 via m16n8k8).
// MODE 0: C = A@B (+R), guards on N (for router N=64)
// MODE 1: MoE gate: A rows gathered via elist, C = gbuf[(e*NTOK+tr)*N + col]
// MODE 2: MoE up:   gathered A; epilogue: gb = silu(gb) * acc * score
// MODE 3: MoE down: A = gbuf slice; epilogue: atomicAdd(out[n*N+col], acc)
#define PADS 136

template<int MODE>
__launch_bounds__(256, 2)
__global__ void mma_gemm(const float* __restrict__ A, const float* __restrict__ B,
                         const float* __restrict__ R, float* __restrict__ C,
                         int M, int N, int K,
                         const int* __restrict__ cnt, const int* __restrict__ elist,
                         const float* __restrict__ escore) {
    __shared__ float As[16 * PADS];   // [k][m], transposed
    __shared__ float Bs[16 * PADS];   // [k][n]
    __shared__ int rows[128];

    const int t = threadIdx.x;
    int e = 0, c = M;
    const int t0 = blockIdx.y * 128;

    if (MODE >= 1) {
        e = blockIdx.z;
        c = cnt[e];
        if (t0 >= c) return;
        B += (size_t)e * K * N;
        if (MODE <= 2) {
            if (t < 128) {
                int tr = t0 + t;
                rows[t] = elist[e * NTOK + (tr < c ? tr : c - 1)];
            }
        } else {
            A += (size_t)e * NTOK * K;
        }
    }
    if (MODE == 1 || MODE == 2) __syncthreads();

    const int bx = blockIdx.x * 128;
    const int lane = t & 31, warp = t >> 5;
    const int lr = lane >> 2, lq = lane & 3;
    const int m0w = (warp & 1) * 64, n0w = (warp >> 1) * 32;

    float acc[4][4][4];
    #pragma unroll
    for (int mt = 0; mt < 4; mt++)
        #pragma unroll
        for (int nt = 0; nt < 4; nt++)
            #pragma unroll
            for (int i = 0; i < 4; i++) acc[mt][nt][i] = 0.f;

    float4 pa[2], pb[2];

    auto loadG = [&](int k0) {
        #pragma unroll
        for (int i = 0; i < 2; i++) {
            int f = t * 2 + i;
            int r = f >> 2, kq = f & 3;
            int gr;
            if (MODE == 0) gr = blockIdx.y * 128 + r;
            else if (MODE == 3) gr = t0 + r;
            else gr = rows[r];
            pa[i] = *(const float4*)&A[(size_t)gr * K + k0 + kq * 4];
            int kr = f >> 5, n = (f & 31) * 4;
            if (bx + n < N)
                pb[i] = *(const float4*)&B[(size_t)(k0 + kr) * N + bx + n];
            else
                pb[i] = make_float4(0.f, 0.f, 0.f, 0.f);
        }
    };
    auto storeS = [&]() {
        #pragma unroll
        for (int i = 0; i < 2; i++) {
            int f = t * 2 + i;
            int r = f >> 2, kq = f & 3;
            const float* av = (const float*)&pa[i];
            #pragma unroll
            for (int j = 0; j < 4; j++) As[(kq * 4 + j) * PADS + r] = tf32r(av[j]);
            int kr = f >> 5, n = (f & 31) * 4;
            const float* bv = (const float*)&pb[i];
            #pragma unroll
            for (int j = 0; j < 4; j++) Bs[kr * PADS + n + j] = tf32r(bv[j]);
        }
    };

    loadG(0);
    storeS();
    for (int k0 = 0; k0 < K; k0 += 16) {
        __syncthreads();
        bool more = (k0 + 16 < K);
        if (more) loadG(k0 + 16);
        #pragma unroll
        for (int ks = 0; ks < 2; ks++) {
            const int kk = ks * 8;
            uint32_t af[4][4], bf[4][2];
            #pragma unroll
            for (int mt = 0; mt < 4; mt++) {
                int m = m0w + mt * 16 + lr;
                af[mt][0] = __float_as_uint(As[(kk + lq) * PADS + m]);
                af[mt][1] = __float_as_uint(As[(kk + lq) * PADS + m + 8]);
                af[mt][2] = __float_as_uint(As[(kk + lq + 4) * PADS + m]);
                af[mt][3] = __float_as_uint(As[(kk + lq + 4) * PADS + m + 8]);
            }
            #pragma unroll
            for (int nt = 0; nt < 4; nt++) {
                int n = n0w + nt * 8 + lr;
                bf[nt][0] = __float_as_uint(Bs[(kk + lq) * PADS + n]);
                bf[nt][1] = __float_as_uint(Bs[(kk + lq + 4) * PADS + n]);
            }
            #pragma unroll
            for (int mt = 0; mt < 4; mt++)
                #pragma unroll
                for (int nt = 0; nt < 4; nt++)
                    mma8(acc[mt][nt], af[mt], bf[nt]);
        }
        __syncthreads();
        if (more) storeS();
    }

    // epilogue
    #pragma unroll
    for (int mt = 0; mt < 4; mt++)
        #pragma unroll
        for (int i = 0; i < 2; i++) {
            int r = m0w + mt * 16 + lr + i * 8;
            #pragma unroll
            for (int nt = 0; nt < 4; nt++) {
                int col = bx + n0w + nt * 8 + lq * 2;
                float v0 = acc[mt][nt][i * 2 + 0];
                float v1 = acc[mt][nt][i * 2 + 1];
                if (MODE == 0) {
                    if (col < N) {
                        int gr = blockIdx.y * 128 + r;
                        size_t o = (size_t)gr * N + col;
                        if (R) { v0 += R[o]; v1 += R[o + 1]; }
                        C[o] = v0; C[o + 1] = v1;
                    }
                } else {
                    int tr = t0 + r;
                    if (tr < c) {
                        if (MODE == 1) {
                            size_t o = ((size_t)e * NTOK + tr) * N + col;
                            C[o] = v0; C[o + 1] = v1;
                        } else if (MODE == 2) {
                            size_t o = ((size_t)e * NTOK + tr) * N + col;
                            float sc = escore[e * NTOK + tr];
                            float g0 = C[o], g1 = C[o + 1];
                            C[o]     = g0 / (1.f + expf(-g0)) * v0 * sc;
                            C[o + 1] = g1 / (1.f + expf(-g1)) * v1 * sc;
                        } else {
                            int n = elist[e * NTOK + tr];
                            atomicAdd(&C[(size_t)n * N + col], v0);
                            atomicAdd(&C[(size_t)n * N + col + 1], v1);
                        }
                    }
                }
            }
        }
}

// ---------------- RoPE (in place) -------------------------------------------
__global__ void rope_kernel(float* __restrict__ q, const float* __restrict__ cs,
                            const float* __restrict__ sn, int nheads) {
    int idx = blockIdx.x * blockDim.x + threadIdx.x;
    int total = NTOK * nheads * 32;
    if (idx >= total) return;
    int d  = idx & 31;
    int hh = (idx >> 5) % nheads;
    int n  = idx / (32 * nheads);
    int tp = n % TSEQ;
    float c0 = cs[tp * HEADD + d],      s0 = sn[tp * HEADD + d];
    float c1 = cs[tp * HEADD + d + 32], s1 = sn[tp * HEADD + d + 32];
    float* base = q + ((size_t)n * nheads + hh) * HEADD;
    float v0 = base[d], v1 = base[d + 32];
    base[d]      = v0 * c0 - v1 * s0;
    base[d + 32] = v1 * c1 + v0 * s1;
}

// ---------------- tiled causal flash attention ------------------------------
// One block per (64-query tile, head, batch). 256 threads. 64x64 key tiles.
__global__ void attn_kernel(const float* __restrict__ Q, const float* __restrict__ Kg,
                            const float* __restrict__ Vg, float* __restrict__ O) {
    extern __shared__ float sm[];
    float* Qs = sm;                       // [64][65]
    float* Ks = sm + 64 * 65;             // [64][65]
    float* Vs = sm + 2 * 64 * 65;         // [64][68]
    float* Ss = sm + 2 * 64 * 65 + 64 * 68; // [64][65]
    __shared__ float m_s[64], l_s[64], corr_s[64];

    int qt = (int)gridDim.x - 1 - (int)blockIdx.x;  // longest blocks first
    int h = blockIdx.y, b = blockIdx.z;
    int kvh = h >> 2;   // NHEAD/NKVH = 4
    int t = threadIdx.x, ty = t >> 4, tx = t & 15;
    int q0 = ty * 4, d0c = tx * 4;

    // load Q tile
    {
        int r = t >> 2, d0 = (t & 3) * 16;
        int n = b * TSEQ + qt * 64 + r;
        const float* src = Q + ((size_t)n * NHEAD + h) * 64 + d0;
        #pragma unroll
        for (int j = 0; j < 16; j += 4) {
            float4 v = *(const float4*)(src + j);
            Qs[r * 65 + d0 + j]     = v.x;
            Qs[r * 65 + d0 + j + 1] = v.y;
            Qs[r * 65 + d0 + j + 2] = v.z;
            Qs[r * 65 + d0 + j + 3] = v.w;
        }
    }
    if (t < 64) { m_s[t] = -1e30f; l_s[t] = 0.f; }

    float o[4][4];
    #pragma unroll
    for (int i = 0; i < 4; i++)
        #pragma unroll
        for (int j = 0; j < 4; j++) o[i][j] = 0.f;

    for (int kt = 0; kt <= qt; kt++) {
        __syncthreads();
        // load K,V tile
        {
            int r = t >> 2, dd0 = (t & 3) * 16;
            int kn = b * TSEQ + kt * 64 + r;
            const float* ks = Kg + ((size_t)kn * NKVH + kvh) * 64 + dd0;
            const float* vs = Vg + ((size_t)kn * NKVH + kvh) * 64 + dd0;
            #pragma unroll
            for (int j = 0; j < 16; j += 4) {
                float4 kv = *(const float4*)(ks + j);
                Ks[r * 65 + dd0 + j]     = kv.x;
                Ks[r * 65 + dd0 + j + 1] = kv.y;
                Ks[r * 65 + dd0 + j + 2] = kv.z;
                Ks[r * 65 + dd0 + j + 3] = kv.w;
                float4 vv = *(const float4*)(vs + j);
                *(float4*)&Vs[r * 68 + dd0 + j] = vv;
            }
        }
        __syncthreads();
        // S = Q K^T (4x4 per thread)
        float s4[4][4];
        #pragma unroll
        for (int i = 0; i < 4; i++)
            #pragma unroll
            for (int j = 0; j < 4; j++) s4[i][j] = 0.f;
        for (int d = 0; d < 64; d++) {
            float a[4], bb[4];
            #pragma unroll
            for (int i = 0; i < 4; i++) a[i] = Qs[(q0 + i) * 65 + d];
            #pragma unroll
            for (int j = 0; j < 4; j++) bb[j] = Ks[(d0c + j) * 65 + d];
            #pragma unroll
            for (int i = 0; i < 4; i++)
                #pragma unroll
                for (int j = 0; j < 4; j++) s4[i][j] += a[i] * bb[j];
        }
        #pragma unroll
        for (int i = 0; i < 4; i++)
            #pragma unroll
            for (int j = 0; j < 4; j++) {
                int kglob = kt * 64 + d0c + j, qglob = qt * 64 + q0 + i;
                Ss[(q0 + i) * 65 + d0c + j] =
                    (kglob <= qglob) ? s4[i][j] * 0.125f : -1e30f;
            }
        __syncthreads();
        // row stats
        if (t < 64) {
            float mx = -1e30f;
            for (int k = 0; k < 64; k++) mx = fmaxf(mx, Ss[t * 65 + k]);
            float newm = fmaxf(m_s[t], mx);
            float corr = expf(m_s[t] - newm);
            float sum = 0.f;
            for (int k = 0; k < 64; k++) sum += expf(Ss[t * 65 + k] - newm);
            l_s[t] = l_s[t] * corr + sum;
            m_s[t] = newm;
            corr_s[t] = corr;
        }
        __syncthreads();
        // P fragments + O rescale
        #pragma unroll
        for (int i = 0; i < 4; i++) {
            float nm = m_s[q0 + i];
            float cr = corr_s[q0 + i];
            #pragma unroll
            for (int j = 0; j < 4; j++) {
                float p = expf(Ss[(q0 + i) * 65 + d0c + j] - nm);
                Ss[(q0 + i) * 65 + d0c + j] = p;
                o[i][j] *= cr;
            }
        }
        __syncthreads();
        // O += P V
        for (int k = 0; k < 64; k++) {
            float a[4];
            #pragma unroll
            for (int i = 0; i < 4; i++) a[i] = Ss[(q0 + i) * 65 + k];
            float4 bv = *(const float4*)&Vs[k * 68 + d0c];
            #pragma unroll
            for (int i = 0; i < 4; i++) {
                o[i][0] += a[i] * bv.x;
                o[i][1] += a[i] * bv.y;
                o[i][2] += a[i] * bv.z;
                o[i][3] += a[i] * bv.w;
            }
        }
    }
    #pragma unroll
    for (int i = 0; i < 4; i++) {
        float inv = 1.f / l_s[q0 + i];
        int n = b * TSEQ + qt * 64 + q0 + i;
        #pragma unroll
        for (int j = 0; j < 4; j++)
            O[(size_t)n * HDIM + h * 64 + d0c + j] = o[i][j] * inv;
    }
}

// ---------------- router ----------------------------------------------------
__global__ void zero_cnt_kernel(int* __restrict__ cnt) {
    if (threadIdx.x < NEXP) cnt[threadIdx.x] = 0;
}

__global__ void router_topk_kernel(const float* __restrict__ logits,
                                   int* __restrict__ cnt, int* __restrict__ elist,
                                   float* __restrict__ escore) {
    int n = blockIdx.x * blockDim.x + threadIdx.x;
    if (n >= NTOK) return;
    float lg[NEXP];
    for (int e = 0; e < NEXP; e++) lg[e] = logits[(size_t)n * NEXP + e];
    int sel[TOPK]; float sv[TOPK];
    for (int k = 0; k < TOPK; k++) {
        float best = -1e30f; int bi = 0;
        for (int e = 0; e < NEXP; e++)
            if (lg[e] > best) { best = lg[e]; bi = e; }
        sel[k] = bi; sv[k] = best; lg[bi] = -1e30f;
    }
    float mx = sv[0];
    float ssum = 0.f;
    for (int k = 0; k < TOPK; k++) { sv[k] = expf(sv[k] - mx); ssum += sv[k]; }
    for (int k = 0; k < TOPK; k++) {
        int e = sel[k];
        int pos = atomicAdd(&cnt[e], 1);
        elist[e * NTOK + pos]  = n;
        escore[e * NTOK + pos] = sv[k] / ssum;
    }
}

// ---------------- launch ----------------------------------------------------
extern "C" void kernel_launch(void* const* d_in, const int* in_sizes, int n_in,
                              void* d_out, int out_size) {
    const float* x    = (const float*)d_in[0];
    const float* cosb = (const float*)d_in[1];
    const float* sinb = (const float*)d_in[2];
    const float* ln1  = (const float*)d_in[3];
    const float* ln2  = (const float*)d_in[4];
    const float* Wq   = (const float*)d_in[5];
    const float* Wk   = (const float*)d_in[6];
    const float* Wv   = (const float*)d_in[7];
    const float* Wo   = (const float*)d_in[8];
    const float* Wr   = (const float*)d_in[9];
    const float* Wg   = (const float*)d_in[10];
    const float* Wu   = (const float*)d_in[11];
    const float* Wd   = (const float*)d_in[12];
    float* out = (float*)d_out;
    float* rl  = out + (size_t)NTOK * HDIM;

    float *h, *q, *k, *v, *ao, *f, *gb, *es;
    int *cnt, *el;
    cudaGetSymbolAddress((void**)&h,   g_h);
    cudaGetSymbolAddress((void**)&q,   g_q);
    cudaGetSymbolAddress((void**)&k,   g_k);
    cudaGetSymbolAddress((void**)&v,   g_v);
    cudaGetSymbolAddress((void**)&ao,  g_ao);
    cudaGetSymbolAddress((void**)&f,   g_f);
    cudaGetSymbolAddress((void**)&gb,  g_gbuf);
    cudaGetSymbolAddress((void**)&es,  g_escore);
    cudaGetSymbolAddress((void**)&cnt, g_cnt);
    cudaGetSymbolAddress((void**)&el,  g_elist);

    const int ATTN_SMEM = (2 * 64 * 65 + 64 * 68 + 64 * 65) * 4; // 67328 B
    cudaFuncSetAttribute(attn_kernel, cudaFuncAttributeMaxDynamicSharedMemorySize,
                         ATTN_SMEM);

    // 1. h = rmsnorm(x, ln1_w)
    rmsnorm_kernel<<<NTOK, 256>>>(x, ln1, h);
    // 2. QKV projections (tf32 mma)
    mma_gemm<0><<<dim3(8, 16), 256>>>(h, Wq, nullptr, q, NTOK, 1024, 1024, nullptr, nullptr, nullptr);
    mma_gemm<0><<<dim3(2, 16), 256>>>(h, Wk, nullptr, k, NTOK,  256, 1024, nullptr, nullptr, nullptr);
    mma_gemm<0><<<dim3(2, 16), 256>>>(h, Wv, nullptr, v, NTOK,  256, 1024, nullptr, nullptr, nullptr);
    // 3. RoPE
    rope_kernel<<<(NTOK * NHEAD * 32 + 255) / 256, 256>>>(q, cosb, sinb, NHEAD);
    rope_kernel<<<(NTOK * NKVH  * 32 + 255) / 256, 256>>>(k, cosb, sinb, NKVH);
    // 4. attention
    attn_kernel<<<dim3(TSEQ / 64, NHEAD, BATCH), 256, ATTN_SMEM>>>(q, k, v, ao);
    // 5. x1 = x + ao@Wo
    mma_gemm<0><<<dim3(8, 16), 256>>>(ao, Wo, x, out, NTOK, 1024, 1024, nullptr, nullptr, nullptr);
    // 6. f = rmsnorm(x1, ln2_w)
    rmsnorm_kernel<<<NTOK, 256>>>(out, ln2, f);
    // 7. router logits
    mma_gemm<0><<<dim3(1, 16), 256>>>(f, Wr, nullptr, rl, NTOK, NEXP, 1024, nullptr, nullptr, nullptr);
    // 8-9. top-k + expert lists
    zero_cnt_kernel<<<1, 64>>>(cnt);
    router_topk_kernel<<<NTOK / 256, 256>>>(rl, cnt, el, es);
    // 10a. gate GEMM -> gb
    mma_gemm<1><<<dim3(IDIM / 128, NTOK / 128, NEXP), 256>>>(f, Wg, nullptr, gb, NTOK, IDIM, 1024, cnt, el, es);
    // 10b. up GEMM, fused silu(gate)*up*score -> gb
    mma_gemm<2><<<dim3(IDIM / 128, NTOK / 128, NEXP), 256>>>(f, Wu, nullptr, gb, NTOK, IDIM, 1024, cnt, el, es);
    // 11. down GEMM + scatter-add onto residual in d_out
    mma_gemm<3><<<dim3(HDIM / 128, NTOK / 128, NEXP), 256>>>(gb, Wd, nullptr, out, NTOK, HDIM, IDIM, cnt, el, es);
}